// round 12
// baseline (speedup 1.0000x reference)
#include <cuda_runtime.h>
#include <math.h>

#define N_VARS 64
#define NV1    65      // N = n_vars + 1
#define M_CL   256
#define KD     12
#define CST    72      // padded C row stride in floats (cols 65..71 zero)
#define HALF   36      // n-range width per lane-half
#define NP     18      // f32x2 pairs per half

// Gram matrix C = Sw^T Sw with ZEROED DIAGONAL, padded rows
__device__ __align__(16) float g_C[NV1 * CST];

typedef unsigned long long u64;

// ---- packed f32x2 primitives (pure PTX, operands stay in u64 pairs) --------
__device__ __forceinline__ u64 ffma2u(u64 a, u64 b, u64 c)
{
    u64 d;
    asm("fma.rn.f32x2 %0, %1, %2, %3;" : "=l"(d) : "l"(a), "l"(b), "l"(c));
    return d;
}
__device__ __forceinline__ u64 fadd2u(u64 a, u64 b)
{
    u64 d;
    asm("add.rn.f32x2 %0, %1, %2;" : "=l"(d) : "l"(a), "l"(b));
    return d;
}
__device__ __forceinline__ u64 pack2(float x, float y)
{
    u64 d;
    asm("mov.b64 %0, {%1, %2};" : "=l"(d) : "f"(x), "f"(y));
    return d;
}
__device__ __forceinline__ void unpack2(u64 p, float& x, float& y)
{
    asm("mov.b64 {%0, %1}, %2;" : "=f"(x), "=f"(y) : "l"(p));
}

// packed dot of one 36-wide C-row half with packed V
__device__ __forceinline__ float dot_half(const float* __restrict__ rowF,
                                          const u64* __restrict__ Vp)
{
    const ulonglong2* cr = (const ulonglong2*)rowF;    // 16B-aligned (CST=72, HALF=36)
    u64 a0 = 0ull, a1 = 0ull, a2 = 0ull, a3 = 0ull;
#pragma unroll
    for (int c = 0; c < 9; ++c) {
        const ulonglong2 cv = cr[c];
        if (c & 1) { a2 = ffma2u(cv.x, Vp[2*c+0], a2); a3 = ffma2u(cv.y, Vp[2*c+1], a3); }
        else       { a0 = ffma2u(cv.x, Vp[2*c+0], a0); a1 = ffma2u(cv.y, Vp[2*c+1], a1); }
    }
    const u64 tt = fadd2u(fadd2u(a0, a2), fadd2u(a1, a3));
    float x, y; unpack2(tt, x, y);
    return x + y;
}

// joint reduce of packed (pp, pg) over the 16-lane group: parallel 2-round
__device__ __forceinline__ u64 reduce16_pair(u64 p)
{
    const unsigned FULL = 0xffffffffu;
    const u64 r1 = __shfl_xor_sync(FULL, p, 4);
    const u64 r2 = __shfl_xor_sync(FULL, p, 8);
    const u64 r3 = __shfl_xor_sync(FULL, p, 12);
    u64 s4 = fadd2u(fadd2u(p, r1), fadd2u(r2, r3));
    const u64 q1 = __shfl_xor_sync(FULL, s4, 1);
    const u64 q2 = __shfl_xor_sync(FULL, s4, 2);
    const u64 q3 = __shfl_xor_sync(FULL, s4, 3);
    return fadd2u(fadd2u(s4, q1), fadd2u(q2, q3));
}

// ---------------------------------------------------------------------------
// Kernel 1: C[i][j] = sum_m (S[m,i]*w[m]) * (S[m,j]*w[m]);  C[i][i] = 0
// ---------------------------------------------------------------------------
__global__ void gram_kernel(const float* __restrict__ S, const float* __restrict__ w)
{
    const int i = blockIdx.x;    // 0..64
    const int j = threadIdx.x;   // 0..71
    float acc = 0.f;
    if (j < NV1) {
#pragma unroll 16
        for (int m = 0; m < M_CL; ++m) {
            const float wm = __ldg(&w[m]);
            acc = fmaf(__ldg(&S[m * NV1 + i]) * wm, __ldg(&S[m * NV1 + j]) * wm, acc);
        }
    }
    g_C[i * CST + j] = (j < NV1 && j != i) ? acc : 0.f;
}

// ---------------------------------------------------------------------------
// Kernel 2: coordinate descent with DEFERRED-NORM recurrence. One warp/batch.
// Lane = h*16 + k, k in [0,12) active, h in {0,1}.
// Lane (h,k) holds V[k][n] for n in [36h, 36h+36) as 18 packed f32x2 regs.
//   g_i  = P_i + c_i v_{i-1}            => g = fma(t, inv, P)
//   s_i  = ||P_i||^2 + c_i^2 - 2 c_i inv_{i-1} (P_i . g_{i-1})
//        = sA - sB * inv_{i-1}          (sA, sB reduced one step early)
// Carried scalar cycle: inv -> s (1 fma) -> fmax -> rsqrt -> inv (~28 cyc).
// ---------------------------------------------------------------------------
__global__ void __launch_bounds__(128, 1)
mix_kernel(const float* __restrict__ z, const float* __restrict__ r,
           const int* __restrict__ miter_p, float* __restrict__ out, int B)
{
    __shared__ __align__(16) float Csh[NV1 * CST];   // 18,720 B
    {
        const float4* src = (const float4*)g_C;
        float4* dst = (float4*)Csh;
#pragma unroll 4
        for (int t = threadIdx.x; t < (NV1 * CST) / 4; t += 128) dst[t] = src[t];
    }
    __syncthreads();

    const int lane = threadIdx.x & 31;
    const int warp = threadIdx.x >> 5;
    const int b    = blockIdx.x * 4 + warp;
    if (b >= B) return;

    const int k = lane & 15;      // component index (0..11 active)
    const int h = lane >> 4;      // which n-half
    const unsigned FULL = 0xffffffffu;
    const float PI = 3.14159265358979323846f;
    const int miter = miter_p ? *miter_p : 12;

    u64 Vp[NP];                   // packed V: pair jp = (n=36h+2jp, n+1)

    // ---- init: V[0]=e0; V[n] = -cos(pi z)e0 + sin(pi z) r_perp_hat ----
#pragma unroll
    for (int jp = 0; jp < NP; ++jp) {
        float vv[2];
#pragma unroll
        for (int q = 0; q < 2; ++q) {
            const int j  = 2 * jp + q;
            const int n  = HALF * h + j;
            const int nc = (n < 1) ? 1 : ((n > 64) ? 64 : n);
            const float zv = z[b * N_VARS + nc - 1];
            const float rv = r[(b * N_VARS + nc - 1) * KD + ((k < KD) ? k : 0)];
            const float rp = (k >= 1 && k < KD) ? rv : 0.f;
            float s = rp * rp;
            s += __shfl_xor_sync(FULL, s, 8);
            s += __shfl_xor_sync(FULL, s, 4);
            s += __shfl_xor_sync(FULL, s, 2);
            s += __shfl_xor_sync(FULL, s, 1);
            const float inv0 = (s > 1e-16f) ? rsqrtf(s) : 1e8f;
            float sn, cs;
            __sincosf(PI * zv, &sn, &cs);
            float v = sn * (rp * inv0);
            if (k == 0) v -= cs;
            const bool active = (n >= 1 && n <= 64);
            vv[q] = active ? v : ((n == 0) ? ((k == 0) ? 1.f : 0.f) : 0.f);
        }
        Vp[jp] = pack2(vv[0], vv[1]);
    }

    // ---- prologue: P_1, sA = ||P_1||^2, sB = 0, t = 0, inv = 0 ----
    float P, sA, sB = 0.f, t = 0.f, inv = 0.f;
    {
        const float acc = dot_half(Csh + 1 * CST + HALF * h, Vp);
        P = acc + __shfl_xor_sync(FULL, acc, 16);
        const u64 red = reduce16_pair(pack2(P * P, 0.f));
        float A, D; unpack2(red, A, D);
        sA = A;
    }

    // ---- sweeps ----
    for (int it = 0; it < miter; ++it) {
#pragma unroll
        for (int i = 1; i < NV1; ++i) {
            const int hi = (i < HALF) ? 0 : 1;    // owning half of coord i
            const int ji = i - HALF * hi;         // element slot in owner
            const int jp = ji >> 1;               // packed slot (compile-time)
            const int inext = (i < 64) ? i + 1 : 1;

            // -------- carried scalar cycle (SHORT) --------
            const float g = fmaf(t, inv, P);           // g_i per-lane
            float s = fmaf(-sB, inv, sA);              // ||g_i||^2 via identity
            s = fmaxf(s, 1e-16f);
            const float invn = rsqrtf(s);              // inv_i

            // -------- off-chain: next-row packed dot --------
            const float cni = Csh[inext * CST + i];    // c_{i+1} = C[i+1][i]
            t = -cni * g;                              // pending coeff for i+1

            float acc = dot_half(Csh + inext * CST + HALF * h, Vp);
            float vx, vy;
            if (h == hi) {
                unpack2(Vp[jp], vx, vy);
                const float vold = (ji & 1) ? vy : vx;
                acc = fmaf(-cni, vold, acc);           // remove OLD V[i] term
            }
            const float Pn = acc + __shfl_xor_sync(FULL, acc, 16);

            // -------- off-chain: reductions for NEXT step's norm -----------
            // A = ||P_{i+1}||^2, D = P_{i+1} . g_i  (joint packed reduce)
            const u64 red = reduce16_pair(pack2(Pn * Pn, Pn * g));
            float A, D; unpack2(red, A, D);
            sA = fmaf(cni, cni, A);                    // ||P||^2 + c^2
            sB = (cni + cni) * D;                      // 2 c D  (times inv_i next step)

            // -------- commit v_i --------
            const float v = -g * invn;
            if (h == hi) {                             // compile-time slot
                if (ji & 1) Vp[jp] = pack2(vx, v);
                else        Vp[jp] = pack2(v, vy);
            }

            P = Pn;
            inv = invn;
        }
    }

    // ---- output: out[b][n-1] = acos(clip(-V[0][n])) / pi ----
    if (k == 0) {
#pragma unroll
        for (int jp = 0; jp < NP; ++jp) {
            float vals[2];
            unpack2(Vp[jp], vals[0], vals[1]);
#pragma unroll
            for (int q = 0; q < 2; ++q) {
                const int n = HALF * h + 2 * jp + q;
                if (n >= 1 && n <= 64) {
                    float c = -vals[q];
                    c = fminf(fmaxf(c, -1.f + 1e-6f), 1.f - 1e-6f);
                    out[b * N_VARS + (n - 1)] = acosf(c) * (1.0f / PI);
                }
            }
        }
    }
}

// ---------------------------------------------------------------------------
extern "C" void kernel_launch(void* const* d_in, const int* in_sizes, int n_in,
                              void* d_out, int out_size)
{
    const float* z = (const float*)d_in[0];
    const float* S = (const float*)d_in[1];
    const float* w = (const float*)d_in[2];
    const float* r = (const float*)d_in[3];
    const int* mi  = (n_in > 4) ? (const int*)d_in[4] : nullptr;
    float* out = (float*)d_out;

    const int B = in_sizes[0] / N_VARS;

    gram_kernel<<<NV1, CST>>>(S, w);
    mix_kernel<<<(B + 3) / 4, 128>>>(z, r, mi, out, B);
}

// round 13
// speedup vs baseline: 1.2146x; 1.2146x over previous
#include <cuda_runtime.h>
#include <math.h>

#define N_VARS 64
#define NV1    65      // N = n_vars + 1
#define M_CL   256
#define KD     12
#define CST    72      // padded C row stride in floats (cols 65..71 zero)
#define HALF   36      // n-range width per lane-half
#define NP     18      // f32x2 pairs per half

// Gram matrix C = Sw^T Sw with ZEROED DIAGONAL, padded rows
__device__ __align__(16) float g_C[NV1 * CST];

typedef unsigned long long u64;

// ---- packed f32x2 primitives (pure PTX, operands stay in u64 pairs) --------
__device__ __forceinline__ u64 ffma2u(u64 a, u64 b, u64 c)
{
    u64 d;
    asm("fma.rn.f32x2 %0, %1, %2, %3;" : "=l"(d) : "l"(a), "l"(b), "l"(c));
    return d;
}
__device__ __forceinline__ u64 fadd2u(u64 a, u64 b)
{
    u64 d;
    asm("add.rn.f32x2 %0, %1, %2;" : "=l"(d) : "l"(a), "l"(b));
    return d;
}
__device__ __forceinline__ u64 pack2(float x, float y)
{
    u64 d;
    asm("mov.b64 %0, {%1, %2};" : "=l"(d) : "f"(x), "f"(y));
    return d;
}
__device__ __forceinline__ void unpack2(u64 p, float& x, float& y)
{
    asm("mov.b64 {%0, %1}, %2;" : "=f"(x), "=f"(y) : "l"(p));
}

// packed dot of one 36-wide C-row half with packed V
__device__ __forceinline__ float dot_half(const float* __restrict__ rowF,
                                          const u64* __restrict__ Vp)
{
    const ulonglong2* cr = (const ulonglong2*)rowF;    // 16B-aligned (CST=72, HALF=36)
    u64 a0 = 0ull, a1 = 0ull, a2 = 0ull, a3 = 0ull;
#pragma unroll
    for (int c = 0; c < 9; ++c) {
        const ulonglong2 cv = cr[c];
        if (c & 1) { a2 = ffma2u(cv.x, Vp[2*c+0], a2); a3 = ffma2u(cv.y, Vp[2*c+1], a3); }
        else       { a0 = ffma2u(cv.x, Vp[2*c+0], a0); a1 = ffma2u(cv.y, Vp[2*c+1], a1); }
    }
    const u64 tt = fadd2u(fadd2u(a0, a2), fadd2u(a1, a3));
    float x, y; unpack2(tt, x, y);
    return x + y;
}

// ---------------------------------------------------------------------------
// Kernel 1: C[i][j] = sum_m (S[m,i]*w[m]) * (S[m,j]*w[m]);  C[i][i] = 0
// 4-way split over m with shared reduction.
// ---------------------------------------------------------------------------
__global__ void gram_kernel(const float* __restrict__ S, const float* __restrict__ w)
{
    __shared__ float part[4][CST];
    const int i  = blockIdx.x;     // 0..64
    const int j  = threadIdx.x;    // 0..71
    const int mm = threadIdx.y;    // 0..3
    float acc = 0.f;
    if (j < NV1) {
        const int m0 = mm * (M_CL / 4);
#pragma unroll 16
        for (int m = m0; m < m0 + M_CL / 4; ++m) {
            const float wm = __ldg(&w[m]);
            acc = fmaf(__ldg(&S[m * NV1 + i]) * wm, __ldg(&S[m * NV1 + j]) * wm, acc);
        }
    }
    part[mm][j] = acc;
    __syncthreads();
    if (mm == 0) {
        const float sum = (part[0][j] + part[1][j]) + (part[2][j] + part[3][j]);
        g_C[i * CST + j] = (j < NV1 && j != i) ? sum : 0.f;
    }
}

// ---------------------------------------------------------------------------
// Kernel 2: coordinate descent, deferred norm + SPLIT-HALF DUAL REDUCTION.
// One warp per batch. Lane = h*16 + k, k in [0,12) active, h in {0,1}.
// Lane (h,k) holds V[k][n] for n in [36h, 36h+36) as 18 packed f32x2 regs.
//   g_i = P_i + c_i v_{i-1}                      => g = fma(t, inv, P)
//   ||g_i||^2 = ||P_i||^2 + c_i^2 - 2 c_i inv_{i-1} (P_i . g_{i-1})
//             = sA_i + sB_i * inv_{i-1}          (sB carries the minus sign)
// A = ||P||^2 reduced in lanes h=0 while D = P.g reduced in lanes h=1
// (P, g identical across halves), then one xor-16 exchange. 8 shfl/step.
// Carried cycle: inv -> s (1 fma) -> fmax -> rsqrt (~28 cyc).
// ---------------------------------------------------------------------------
__global__ void __launch_bounds__(128, 1)
mix_kernel(const float* __restrict__ z, const float* __restrict__ r,
           const int* __restrict__ miter_p, float* __restrict__ out, int B)
{
    __shared__ __align__(16) float Csh[NV1 * CST];   // 18,720 B
    {
        const float4* src = (const float4*)g_C;
        float4* dst = (float4*)Csh;
#pragma unroll 4
        for (int t = threadIdx.x; t < (NV1 * CST) / 4; t += 128) dst[t] = src[t];
    }
    __syncthreads();

    const int lane = threadIdx.x & 31;
    const int warp = threadIdx.x >> 5;
    const int b    = blockIdx.x * 4 + warp;
    if (b >= B) return;

    const int k = lane & 15;      // component index (0..11 active)
    const int h = lane >> 4;      // which n-half
    const unsigned FULL = 0xffffffffu;
    const float PI = 3.14159265358979323846f;
    const int miter = miter_p ? *miter_p : 12;

    u64 Vp[NP];                   // packed V: pair jp = (n=36h+2jp, n+1)

    // ---- init: V[0]=e0; V[n] = -cos(pi z)e0 + sin(pi z) r_perp_hat ----
#pragma unroll
    for (int jp = 0; jp < NP; ++jp) {
        float vv[2];
#pragma unroll
        for (int q = 0; q < 2; ++q) {
            const int j  = 2 * jp + q;
            const int n  = HALF * h + j;
            const int nc = (n < 1) ? 1 : ((n > 64) ? 64 : n);
            const float zv = z[b * N_VARS + nc - 1];
            const float rv = r[(b * N_VARS + nc - 1) * KD + ((k < KD) ? k : 0)];
            const float rp = (k >= 1 && k < KD) ? rv : 0.f;
            float s = rp * rp;
            s += __shfl_xor_sync(FULL, s, 8);
            s += __shfl_xor_sync(FULL, s, 4);
            s += __shfl_xor_sync(FULL, s, 2);
            s += __shfl_xor_sync(FULL, s, 1);
            const float inv0 = (s > 1e-16f) ? rsqrtf(s) : 1e8f;
            float sn, cs;
            __sincosf(PI * zv, &sn, &cs);
            float v = sn * (rp * inv0);
            if (k == 0) v -= cs;
            const bool active = (n >= 1 && n <= 64);
            vv[q] = active ? v : ((n == 0) ? ((k == 0) ? 1.f : 0.f) : 0.f);
        }
        Vp[jp] = pack2(vv[0], vv[1]);
    }

    // ---- prologue: P_1 and sA = ||P_1||^2 (g_0 = 0 -> D = 0, sB = 0) ----
    float P, sA, sB = 0.f, t = 0.f, inv = 0.f;
    {
        const float acc = dot_half(Csh + 1 * CST + HALF * h, Vp);
        P = acc + __shfl_xor_sync(FULL, acc, 16);
        // dual reduce with g=0: h=0 lanes reduce P*P, h=1 lanes reduce 0
        const float x = h ? 0.f : P * P;
        const float r1 = __shfl_xor_sync(FULL, x, 4);
        const float r2 = __shfl_xor_sync(FULL, x, 8);
        const float r3 = __shfl_xor_sync(FULL, x, 12);
        float s4 = (x + r1) + (r2 + r3);
        const float q1 = __shfl_xor_sync(FULL, s4, 1);
        const float q2 = __shfl_xor_sync(FULL, s4, 2);
        const float q3 = __shfl_xor_sync(FULL, s4, 3);
        const float xr = (s4 + q1) + (q2 + q3);
        const float other = __shfl_xor_sync(FULL, xr, 16);
        sA = h ? other : xr;
    }

    // ---- sweeps ----
    for (int it = 0; it < miter; ++it) {
#pragma unroll
        for (int i = 1; i < NV1; ++i) {
            const int hi = (i < HALF) ? 0 : 1;    // owning half of coord i
            const int ji = i - HALF * hi;         // element slot in owner
            const int jp = ji >> 1;               // packed slot (compile-time)
            const int inext = (i < 64) ? i + 1 : 1;

            // -------- carried scalar cycle (SHORT) --------
            const float g = fmaf(t, inv, P);           // g_i per-lane
            float s = fmaf(sB, inv, sA);               // ||g_i||^2 via identity
            s = fmaxf(s, 1e-16f);
            const float invn = rsqrtf(s);              // inv_i

            // -------- off-chain: next-row packed dot --------
            const float cni = Csh[inext * CST + i];    // c_{i+1} = C[i+1][i]
            t = -cni * g;                              // pending coeff for i+1

            float acc = dot_half(Csh + inext * CST + HALF * h, Vp);
            float vx, vy;
            if (h == hi) {
                unpack2(Vp[jp], vx, vy);
                const float vold = (ji & 1) ? vy : vx;
                acc = fmaf(-cni, vold, acc);           // remove OLD V[i] term
            }
            const float Pn = acc + __shfl_xor_sync(FULL, acc, 16);

            // -------- off-chain: dual reduction (A in h=0, D in h=1) --------
            const float x = Pn * (h ? g : Pn);
            const float r1 = __shfl_xor_sync(FULL, x, 4);
            const float r2 = __shfl_xor_sync(FULL, x, 8);
            const float r3 = __shfl_xor_sync(FULL, x, 12);
            float s4 = (x + r1) + (r2 + r3);
            const float q1 = __shfl_xor_sync(FULL, s4, 1);
            const float q2 = __shfl_xor_sync(FULL, s4, 2);
            const float q3 = __shfl_xor_sync(FULL, s4, 3);
            const float xr = (s4 + q1) + (q2 + q3);
            const float other = __shfl_xor_sync(FULL, xr, 16);
            const float A = h ? other : xr;            // ||P_{i+1}||^2
            const float D = h ? xr : other;            // P_{i+1} . g_i
            sA = fmaf(cni, cni, A);                    // ||P||^2 + c^2
            sB = (-2.f * cni) * D;                     // -(2c)D, times inv_i later

            // -------- commit v_i --------
            const float v = -g * invn;
            if (h == hi) {                             // compile-time slot
                if (ji & 1) Vp[jp] = pack2(vx, v);
                else        Vp[jp] = pack2(v, vy);
            }

            P = Pn;
            inv = invn;
        }
    }

    // ---- output: out[b][n-1] = acos(clip(-V[0][n])) / pi ----
    if (k == 0) {
#pragma unroll
        for (int jp = 0; jp < NP; ++jp) {
            float vals[2];
            unpack2(Vp[jp], vals[0], vals[1]);
#pragma unroll
            for (int q = 0; q < 2; ++q) {
                const int n = HALF * h + 2 * jp + q;
                if (n >= 1 && n <= 64) {
                    float c = -vals[q];
                    c = fminf(fmaxf(c, -1.f + 1e-6f), 1.f - 1e-6f);
                    out[b * N_VARS + (n - 1)] = acosf(c) * (1.0f / PI);
                }
            }
        }
    }
}

// ---------------------------------------------------------------------------
extern "C" void kernel_launch(void* const* d_in, const int* in_sizes, int n_in,
                              void* d_out, int out_size)
{
    const float* z = (const float*)d_in[0];
    const float* S = (const float*)d_in[1];
    const float* w = (const float*)d_in[2];
    const float* r = (const float*)d_in[3];
    const int* mi  = (n_in > 4) ? (const int*)d_in[4] : nullptr;
    float* out = (float*)d_out;

    const int B = in_sizes[0] / N_VARS;

    gram_kernel<<<NV1, dim3(CST, 4)>>>(S, w);
    mix_kernel<<<(B + 3) / 4, 128>>>(z, r, mi, out, B);
}

// round 14
// speedup vs baseline: 1.3809x; 1.1369x over previous
#include <cuda_runtime.h>
#include <math.h>

#define N_VARS 64
#define NV1    65      // N = n_vars + 1
#define M_CL   256
#define KD     12
#define CST    72      // padded C row stride in floats (cols 65..71 zero)
#define HALF   36      // n-range width per lane-half
#define NP     18      // f32x2 pairs per half

// Gram matrix C = Sw^T Sw with ZEROED DIAGONAL, padded rows
__device__ __align__(16) float g_C[NV1 * CST];

typedef unsigned long long u64;

// ---- packed f32x2 primitives (pure PTX, operands stay in u64 pairs) --------
__device__ __forceinline__ u64 ffma2u(u64 a, u64 b, u64 c)
{
    u64 d;
    asm("fma.rn.f32x2 %0, %1, %2, %3;" : "=l"(d) : "l"(a), "l"(b), "l"(c));
    return d;
}
__device__ __forceinline__ u64 fadd2u(u64 a, u64 b)
{
    u64 d;
    asm("add.rn.f32x2 %0, %1, %2;" : "=l"(d) : "l"(a), "l"(b));
    return d;
}
__device__ __forceinline__ u64 pack2(float x, float y)
{
    u64 d;
    asm("mov.b64 %0, {%1, %2};" : "=l"(d) : "f"(x), "f"(y));
    return d;
}
__device__ __forceinline__ void unpack2(u64 p, float& x, float& y)
{
    asm("mov.b64 {%0, %1}, %2;" : "=f"(x), "=f"(y) : "l"(p));
}

// packed dot of one 36-wide C-row half with packed V
__device__ __forceinline__ float dot_half(const float* __restrict__ rowF,
                                          const u64* __restrict__ Vp)
{
    const ulonglong2* cr = (const ulonglong2*)rowF;    // 16B-aligned (CST=72, HALF=36)
    u64 a0 = 0ull, a1 = 0ull, a2 = 0ull, a3 = 0ull;
#pragma unroll
    for (int c = 0; c < 9; ++c) {
        const ulonglong2 cv = cr[c];
        if (c & 1) { a2 = ffma2u(cv.x, Vp[2*c+0], a2); a3 = ffma2u(cv.y, Vp[2*c+1], a3); }
        else       { a0 = ffma2u(cv.x, Vp[2*c+0], a0); a1 = ffma2u(cv.y, Vp[2*c+1], a1); }
    }
    const u64 tt = fadd2u(fadd2u(a0, a2), fadd2u(a1, a3));
    float x, y; unpack2(tt, x, y);
    return x + y;
}

// ---------------------------------------------------------------------------
// Kernel 1: C[i][j] = sum_m (S[m,i]*w[m]) * (S[m,j]*w[m]);  C[i][i] = 0
// 4-way split over m with shared reduction (R13 version: ~1 us).
// ---------------------------------------------------------------------------
__global__ void gram_kernel(const float* __restrict__ S, const float* __restrict__ w)
{
    __shared__ float part[4][CST];
    const int i  = blockIdx.x;     // 0..64
    const int j  = threadIdx.x;    // 0..71
    const int mm = threadIdx.y;    // 0..3
    float acc = 0.f;
    if (j < NV1) {
        const int m0 = mm * (M_CL / 4);
#pragma unroll 16
        for (int m = m0; m < m0 + M_CL / 4; ++m) {
            const float wm = __ldg(&w[m]);
            acc = fmaf(__ldg(&S[m * NV1 + i]) * wm, __ldg(&S[m * NV1 + j]) * wm, acc);
        }
    }
    part[mm][j] = acc;
    __syncthreads();
    if (mm == 0) {
        const float sum = (part[0][j] + part[1][j]) + (part[2][j] + part[3][j]);
        g_C[i * CST + j] = (j < NV1 && j != i) ? sum : 0.f;
    }
}

// ---------------------------------------------------------------------------
// Kernel 2: pipelined coordinate descent (R5, verbatim). One warp per batch.
// Lane = h*16 + k, k in [0,12) active, h in {0,1}.
// Lane (h,k) holds V[k][n] for n in [36h, 36h+36) as 18 packed f32x2 regs.
// Recurrence: g_i = P_i + C[i,i-1]*v_{i-1}  =>  g = fma(t, inv, P)
// ---------------------------------------------------------------------------
__global__ void __launch_bounds__(128, 1)
mix_kernel(const float* __restrict__ z, const float* __restrict__ r,
           const int* __restrict__ miter_p, float* __restrict__ out, int B)
{
    __shared__ __align__(16) float Csh[NV1 * CST];   // 18,720 B
    {
        const float4* src = (const float4*)g_C;
        float4* dst = (float4*)Csh;
#pragma unroll 4
        for (int t = threadIdx.x; t < (NV1 * CST) / 4; t += 128) dst[t] = src[t];
    }
    __syncthreads();

    const int lane = threadIdx.x & 31;
    const int warp = threadIdx.x >> 5;
    const int b    = blockIdx.x * 4 + warp;
    if (b >= B) return;

    const int k = lane & 15;      // component index (0..11 active)
    const int h = lane >> 4;      // which n-half
    const unsigned FULL = 0xffffffffu;
    const float PI = 3.14159265358979323846f;
    const int miter = miter_p ? *miter_p : 12;

    u64 Vp[NP];                   // packed V: pair jp = (n=36h+2jp, n+1)

    // ---- init: V[0]=e0; V[n] = -cos(pi z)e0 + sin(pi z) r_perp_hat ----
#pragma unroll
    for (int jp = 0; jp < NP; ++jp) {
        float vv[2];
#pragma unroll
        for (int q = 0; q < 2; ++q) {
            const int j  = 2 * jp + q;
            const int n  = HALF * h + j;
            const int nc = (n < 1) ? 1 : ((n > 64) ? 64 : n);
            const float zv = z[b * N_VARS + nc - 1];
            const float rv = r[(b * N_VARS + nc - 1) * KD + ((k < KD) ? k : 0)];
            const float rp = (k >= 1 && k < KD) ? rv : 0.f;
            float s = rp * rp;
            s += __shfl_xor_sync(FULL, s, 8);
            s += __shfl_xor_sync(FULL, s, 4);
            s += __shfl_xor_sync(FULL, s, 2);
            s += __shfl_xor_sync(FULL, s, 1);
            const float inv0 = (s > 1e-16f) ? rsqrtf(s) : 1e8f;
            float sn, cs;
            __sincosf(PI * zv, &sn, &cs);
            float v = sn * (rp * inv0);
            if (k == 0) v -= cs;
            const bool active = (n >= 1 && n <= 64);
            vv[q] = active ? v : ((n == 0) ? ((k == 0) ? 1.f : 0.f) : 0.f);
        }
        Vp[jp] = pack2(vv[0], vv[1]);
    }

    // ---- pipelined sweeps ----
    float P, t = 0.f, inv = 0.f;

    // prologue: P = full dot of row 1 (no pending coordinate)
    {
        const float acc = dot_half(Csh + 1 * CST + HALF * h, Vp);
        P = acc + __shfl_xor_sync(FULL, acc, 16);
    }

    for (int it = 0; it < miter; ++it) {
#pragma unroll
        for (int i = 1; i < NV1; ++i) {
            const int hi = (i < HALF) ? 0 : 1;    // owning half of coord i
            const int ji = i - HALF * hi;         // element slot in owner
            const int jp = ji >> 1;               // packed slot (compile-time)
            const int inext = (i < 64) ? i + 1 : 1;

            // -------- critical chain: g, ||g||^2 --------
            const float g = fmaf(t, inv, P);

            const float c1 = __shfl_xor_sync(FULL, g, 4);
            const float c2 = __shfl_xor_sync(FULL, g, 8);
            const float c3 = __shfl_xor_sync(FULL, g, 12);
            float s4 = g * g;
            s4 = fmaf(c1, c1, s4);
            s4 = fmaf(c2, c2, s4);
            s4 = fmaf(c3, c3, s4);
            const float d1 = __shfl_xor_sync(FULL, s4, 1);
            const float d2 = __shfl_xor_sync(FULL, s4, 2);
            const float d3 = __shfl_xor_sync(FULL, s4, 3);
            float s = (s4 + d1) + (d2 + d3);
            s = fmaxf(s, 1e-16f);

            // -------- off-chain: next-row packed dot --------
            const float cni = Csh[inext * CST + i];   // C[inext][i]
            t = -cni * g;                             // pending-term coeff

            float acc = dot_half(Csh + inext * CST + HALF * h, Vp);

            float vx, vy;
            if (h == hi) {
                unpack2(Vp[jp], vx, vy);
                const float vold = (ji & 1) ? vy : vx;
                acc = fmaf(-cni, vold, acc);          // remove OLD V[i] term
            }
            P = acc + __shfl_xor_sync(FULL, acc, 16);

            // -------- finish chain, commit v_i --------
            inv = rsqrtf(s);
            const float v = -g * inv;
            if (h == hi) {                            // compile-time slot
                if (ji & 1) Vp[jp] = pack2(vx, v);
                else        Vp[jp] = pack2(v, vy);
            }
        }
    }

    // ---- output: out[b][n-1] = acos(clip(-V[0][n])) / pi ----
    if (k == 0) {
#pragma unroll
        for (int jp = 0; jp < NP; ++jp) {
            float vals[2];
            unpack2(Vp[jp], vals[0], vals[1]);
#pragma unroll
            for (int q = 0; q < 2; ++q) {
                const int n = HALF * h + 2 * jp + q;
                if (n >= 1 && n <= 64) {
                    float c = -vals[q];
                    c = fminf(fmaxf(c, -1.f + 1e-6f), 1.f - 1e-6f);
                    out[b * N_VARS + (n - 1)] = acosf(c) * (1.0f / PI);
                }
            }
        }
    }
}

// ---------------------------------------------------------------------------
extern "C" void kernel_launch(void* const* d_in, const int* in_sizes, int n_in,
                              void* d_out, int out_size)
{
    const float* z = (const float*)d_in[0];
    const float* S = (const float*)d_in[1];
    const float* w = (const float*)d_in[2];
    const float* r = (const float*)d_in[3];
    const int* mi  = (n_in > 4) ? (const int*)d_in[4] : nullptr;
    float* out = (float*)d_out;

    const int B = in_sizes[0] / N_VARS;

    gram_kernel<<<NV1, dim3(CST, 4)>>>(S, w);
    mix_kernel<<<(B + 3) / 4, 128>>>(z, r, mi, out, B);
}